// round 12
// baseline (speedup 1.0000x reference)
#include <cuda_runtime.h>
#include <cstdint>

#define NS 25
#define NC 80
#define CD 6400
#define BT 25600

#define MTB 128              // M rows per tile
#define NTB 128              // N cols per block stripe
#define THREADS 128
#define NXB 50               // 6400/128
#define NYB 11               // 50*11 = 550 blocks (single wave at 4/SM)
#define MTILES 200           // 25600/128

#define PL 16                // k2 planes (K padded to 32)
#define PSTR 132             // uint2 elements per plane (conflict-free)

__device__ __forceinline__ uint16_t f2bf(float v) {
    uint16_t r;
    asm("cvt.rn.bf16.f32 %0, %1;" : "=h"(r) : "f"(v));
    return r;
}
__device__ __forceinline__ float bf2f(uint16_t h) {
    return __uint_as_float((uint32_t)h << 16);
}
__device__ __forceinline__ void mma_bf16(float* acc, const uint32_t* a,
                                         uint32_t b0, uint32_t b1) {
    asm volatile(
        "mma.sync.aligned.m16n8k16.row.col.f32.bf16.bf16.f32 "
        "{%0,%1,%2,%3}, {%4,%5,%6,%7}, {%8,%9}, {%0,%1,%2,%3};"
        : "+f"(acc[0]), "+f"(acc[1]), "+f"(acc[2]), "+f"(acc[3])
        : "r"(a[0]), "r"(a[1]), "r"(a[2]), "r"(a[3]), "r"(b0), "r"(b1));
}

// ---------------------------------------------------------------------------
// C = A @ D_flat via bf16 3-term split. Persistent N-stripe blocks.
// Epilogue: 32-col chunks staged through per-warp smem -> coalesced STG.128.
// ---------------------------------------------------------------------------
__global__ __launch_bounds__(THREADS, 4)
void tc_kernel(const float* __restrict__ alpha,
               const float* __restrict__ D,
               const float* __restrict__ asc,
               float* __restrict__ C)
{
    __shared__ uint2 AHL[PL * PSTR];       // 16.9 KB
    __shared__ uint2 BHL[PL * PSTR];       // 16.9 KB
    __shared__ __align__(16) float stage[4 * 32 * 32];   // 16 KB, 4 KB per warp
    __shared__ float scale_s[32];

    const int tid = threadIdx.x;
    if (tid < NS) scale_s[tid] = log1pf(expf(asc[tid]));

    // zero plane arrays (covers k=25..31 padding)
    {
        uint4* z = reinterpret_cast<uint4*>(AHL);
        for (int i = tid; i < (PL * PSTR) / 2; i += THREADS) z[i] = make_uint4(0,0,0,0);
        uint4* z2 = reinterpret_cast<uint4*>(BHL);
        for (int i = tid; i < (PL * PSTR) / 2; i += THREADS) z2[i] = make_uint4(0,0,0,0);
    }
    __syncthreads();

    const int nb = blockIdx.x * NTB;

    // ---- B split (once per block) ----
    for (int i = tid; i < NS * NTB; i += THREADS) {
        const int k = i >> 7, n = i & 127;
        const float v = D[(size_t)k * CD + nb + n];
        const uint16_t h = f2bf(v);
        const uint16_t l = f2bf(v - bf2f(h));
        char* base = reinterpret_cast<char*>(&BHL[(k >> 1) * PSTR + n]);
        *reinterpret_cast<uint16_t*>(base + (k & 1) * 2)     = h;
        *reinterpret_cast<uint16_t*>(base + 4 + (k & 1) * 2) = l;
    }

    const int w = tid >> 5, lane = tid & 31;
    const int grp = lane >> 2, kk = lane & 3;
    float* stg = stage + w * 1024;

    for (int mt = blockIdx.y; mt < MTILES; mt += NYB) {
        const int m0 = mt * MTB;

        __syncthreads();
        // ---- A split ----
        {
            const float* ap = alpha + (size_t)m0 * NS;
            #pragma unroll
            for (int t = 0; t < (MTB * NS) / THREADS; t++) {
                const int i = tid + t * THREADS;
                const int r = i / NS, k = i - r * NS;
                const float v = ap[i] * scale_s[k];
                const uint16_t h = f2bf(v);
                const uint16_t l = f2bf(v - bf2f(h));
                char* base = reinterpret_cast<char*>(&AHL[(k >> 1) * PSTR + r]);
                *reinterpret_cast<uint16_t*>(base + (k & 1) * 2)     = h;
                *reinterpret_cast<uint16_t*>(base + 4 + (k & 1) * 2) = l;
            }
        }
        __syncthreads();

        // ---- a-fragments (hi+lo), register-resident ----
        uint32_t ah[2][2][4], al[2][2][4];
        #pragma unroll
        for (int m = 0; m < 2; m++) {
            const int rb = w * 32 + m * 16 + grp;
            #pragma unroll
            for (int g = 0; g < 2; g++) {
                const int p0 = (g * 8 + kk) * PSTR, p1 = p0 + 4 * PSTR;
                uint2 t;
                t = AHL[p0 + rb];     ah[m][g][0] = t.x; al[m][g][0] = t.y;
                t = AHL[p0 + rb + 8]; ah[m][g][1] = t.x; al[m][g][1] = t.y;
                t = AHL[p1 + rb];     ah[m][g][2] = t.x; al[m][g][2] = t.y;
                t = AHL[p1 + rb + 8]; ah[m][g][3] = t.x; al[m][g][3] = t.y;
            }
        }

        // ---- 4 chunks of 32 contiguous columns ----
        #pragma unroll 1
        for (int ch = 0; ch < 4; ch++) {
            float acc[2][4][4];
            #pragma unroll
            for (int m = 0; m < 2; m++)
                #pragma unroll
                for (int sp = 0; sp < 4; sp++)
                    #pragma unroll
                    for (int q = 0; q < 4; q++) acc[m][sp][q] = 0.f;

            #pragma unroll
            for (int g = 0; g < 2; g++) {
                const int p0 = (g * 8 + kk) * PSTR, p1 = p0 + 4 * PSTR;
                #pragma unroll
                for (int sp = 0; sp < 4; sp++) {
                    const int n_c = ch * 32 + sp * 8 + grp;
                    const uint2 b0 = BHL[p0 + n_c];
                    const uint2 b1 = BHL[p1 + n_c];
                    #pragma unroll
                    for (int m = 0; m < 2; m++) {
                        mma_bf16(acc[m][sp], ah[m][g], b0.x, b1.x);
                        mma_bf16(acc[m][sp], al[m][g], b0.x, b1.x);
                        mma_bf16(acc[m][sp], ah[m][g], b0.y, b1.y);
                    }
                }
            }

            // ---- stage chunk to per-warp smem (swizzled, conflict-free) ----
            #pragma unroll
            for (int m = 0; m < 2; m++) {
                const int row = m * 16 + grp;
                const int s0 = (row & 3) << 2;
                #pragma unroll
                for (int sp = 0; sp < 4; sp++) {
                    const int c2 = (sp * 4 + kk) ^ s0;
                    *reinterpret_cast<float2*>(&stg[row * 32 + (c2 << 1)]) =
                        make_float2(acc[m][sp][0], acc[m][sp][1]);
                    *reinterpret_cast<float2*>(&stg[(row + 8) * 32 + (c2 << 1)]) =
                        make_float2(acc[m][sp][2], acc[m][sp][3]);
                }
            }
            __syncwarp();

            // ---- coalesced STG.128: 4 full 128B rows per instruction ----
            float* Cb = C + (size_t)(m0 + w * 32) * CD + nb + ch * 32;
            #pragma unroll
            for (int it = 0; it < 8; it++) {
                const int ro = (lane >> 3) + it * 4;
                const int q  = lane & 7;
                const int c2 = (2 * q) ^ ((ro & 3) << 2);
                const float4 v = *reinterpret_cast<const float4*>(&stg[ro * 32 + (c2 << 1)]);
                __stcs(reinterpret_cast<float4*>(Cb + (size_t)ro * CD + q * 4), v);
            }
            __syncwarp();
        }
    }
}

// ---------------------------------------------------------------------------
// m_t = A @ mu (tiny)
// ---------------------------------------------------------------------------
__global__ __launch_bounds__(256)
void m_kernel(const float* __restrict__ alpha,
              const float* __restrict__ mu,
              const float* __restrict__ asc,
              float* __restrict__ m)
{
    __shared__ float mu_s[NS * NC];
    __shared__ float a_s[16 * NS];
    __shared__ float scale_s[NS];

    const int tid = threadIdx.x;
    if (tid < NS) scale_s[tid] = log1pf(expf(asc[tid]));
    __syncthreads();

    for (int i = tid; i < NS * NC; i += 256) mu_s[i] = mu[i];

    const int bt0 = blockIdx.x * 16;
    for (int i = tid; i < 16 * NS; i += 256) {
        const int r = i / NS, j = i % NS;
        a_s[i] = alpha[(bt0 + r) * NS + j] * scale_s[j];
    }
    __syncthreads();

    for (int o = tid; o < 16 * NC; o += 256) {
        const int r = o / NC, c = o % NC;
        float s = 0.0f;
        #pragma unroll
        for (int j = 0; j < NS; j++) s = fmaf(a_s[r * NS + j], mu_s[j * NC + c], s);
        m[(size_t)(bt0 + r) * NC + c] = s;
    }
}

extern "C" void kernel_launch(void* const* d_in, const int* in_sizes, int n_in,
                              void* d_out, int out_size)
{
    const float* alpha = (const float*)d_in[0];   // [64,400,25]
    const float* mu    = (const float*)d_in[1];   // [25,80]
    const float* D     = (const float*)d_in[2];   // [25,80,80]
    const float* asc   = (const float*)d_in[3];   // [25]

    float* out   = (float*)d_out;
    float* m_out = out;                 // [64,400,80]
    float* c_out = out + (BT * NC);     // [64,400,80,80]

    m_kernel<<<BT / 16, 256>>>(alpha, mu, asc, m_out);
    tc_kernel<<<dim3(NXB, NYB), THREADS>>>(alpha, D, asc, c_out);
}

// round 13
// speedup vs baseline: 1.4838x; 1.4838x over previous
#include <cuda_runtime.h>
#include <cstdint>

#define NS 25
#define NC 80
#define CD 6400
#define BT 25600

#define MTB 128              // M rows per block tile
#define NTB 128              // N cols per block stripe
#define THREADS 256
#define NXB 50               // 6400/128
#define NYB 8                // 50*8 = 400 persistent blocks
#define MTILES 200           // 25600/128

#define PL 16                // k-pair planes (K padded to 32)
#define PSTR 132             // uint2 elements per plane

__device__ __forceinline__ uint16_t f2bf(float v) {
    uint16_t r;
    asm("cvt.rn.bf16.f32 %0, %1;" : "=h"(r) : "f"(v));
    return r;
}
__device__ __forceinline__ float bf2f(uint16_t h) {
    return __uint_as_float((uint32_t)h << 16);
}
__device__ __forceinline__ void mma_bf16(float* acc, const uint32_t* a,
                                         uint32_t b0, uint32_t b1) {
    asm volatile(
        "mma.sync.aligned.m16n8k16.row.col.f32.bf16.bf16.f32 "
        "{%0,%1,%2,%3}, {%4,%5,%6,%7}, {%8,%9}, {%0,%1,%2,%3};"
        : "+f"(acc[0]), "+f"(acc[1]), "+f"(acc[2]), "+f"(acc[3])
        : "r"(a[0]), "r"(a[1]), "r"(a[2]), "r"(a[3]), "r"(b0), "r"(b1));
}

// plane-local index with XOR swizzle (conflict-free fragment LDS)
__device__ __forceinline__ int pidx(int plane, int x) {
    return plane * PSTR + (x ^ ((plane & 3) << 3));
}

// ---------------------------------------------------------------------------
// C = A @ D_flat, bf16 3-term split (Ah*Bh + Al*Bh + Ah*Bl).
// Persistent N-stripe blocks; 8 warps; warp = 32 rows x 64 cols.
// ---------------------------------------------------------------------------
__global__ __launch_bounds__(THREADS, 3)
void tc_kernel(const float* __restrict__ alpha,
               const float* __restrict__ D,
               const float* __restrict__ asc,
               float* __restrict__ C)
{
    __shared__ uint2 AHL[PL * PSTR];    // 16.9 KB
    __shared__ uint2 BHL[PL * PSTR];    // 16.9 KB
    __shared__ float scale_s[32];

    const int tid = threadIdx.x;
    if (tid < NS) scale_s[tid] = log1pf(expf(asc[tid]));

    // zero pad planes 13..15 of A and B (read by g=1 MMA, never written)
    for (int i = tid; i < 3 * PSTR; i += THREADS) {
        AHL[13 * PSTR + i] = make_uint2(0, 0);
        BHL[13 * PSTR + i] = make_uint2(0, 0);
    }

    const int nb = blockIdx.x * NTB;

    // ---- B split (once per block): packed k-pairs, swizzled ----
    for (int it = tid; it < 13 * NTB; it += THREADS) {
        const int kp = it >> 7, n = it & 127;       // coalesced over n
        const float v0 = D[(size_t)(2 * kp) * CD + nb + n];
        const float v1 = (2 * kp + 1 < NS) ? D[(size_t)(2 * kp + 1) * CD + nb + n] : 0.f;
        const uint16_t h0 = f2bf(v0), h1 = f2bf(v1);
        const uint16_t l0 = f2bf(v0 - bf2f(h0)), l1 = f2bf(v1 - bf2f(h1));
        BHL[pidx(kp, n)] = make_uint2((uint32_t)h0 | ((uint32_t)h1 << 16),
                                      (uint32_t)l0 | ((uint32_t)l1 << 16));
    }

    const int w = tid >> 5, lane = tid & 31;
    const int grp = lane >> 2, kk = lane & 3;
    const int rowg = w >> 1;             // 0..3 -> rows rowg*32
    const int sh   = w & 1;              // 0/1  -> cols sh*64
    const int kkx  = kk << 3;

    for (int mt = blockIdx.y; mt < MTILES; mt += NYB) {
        const int m0 = mt * MTB;

        __syncthreads();
        // ---- A split: coalesced read, packed sub-word writes, swizzled ----
        {
            const float* ap = alpha + (size_t)m0 * NS;
            for (int i = tid; i < MTB * NS; i += THREADS) {
                const int r = i / NS, k = i - r * NS;
                const float v = ap[i] * scale_s[k];
                const uint16_t h = f2bf(v);
                const uint16_t l = f2bf(v - bf2f(h));
                char* base = reinterpret_cast<char*>(&AHL[pidx(k >> 1, r)]);
                *reinterpret_cast<uint16_t*>(base + (k & 1) * 2)     = h;
                *reinterpret_cast<uint16_t*>(base + 4 + (k & 1) * 2) = l;
            }
        }
        __syncthreads();

        // ---- a-fragments (hi+lo), register-resident: 32 regs ----
        uint32_t ah[2][2][4], al[2][2][4];
        #pragma unroll
        for (int m = 0; m < 2; m++) {
            const int rb = rowg * 32 + m * 16 + grp;
            #pragma unroll
            for (int g = 0; g < 2; g++) {
                const int p0 = g * 8 + kk;
                uint2 t;
                t = AHL[p0 * PSTR + ((rb)      ^ kkx)]; ah[m][g][0] = t.x; al[m][g][0] = t.y;
                t = AHL[p0 * PSTR + ((rb + 8)  ^ kkx)]; ah[m][g][1] = t.x; al[m][g][1] = t.y;
                t = AHL[(p0 + 4) * PSTR + ((rb)     ^ kkx)]; ah[m][g][2] = t.x; al[m][g][2] = t.y;
                t = AHL[(p0 + 4) * PSTR + ((rb + 8) ^ kkx)]; ah[m][g][3] = t.x; al[m][g][3] = t.y;
            }
        }

        #pragma unroll
        for (int sp = 0; sp < 8; sp++) {
            float acc[2][4];
            #pragma unroll
            for (int m = 0; m < 2; m++)
                #pragma unroll
                for (int q = 0; q < 4; q++) acc[m][q] = 0.f;

            const int nloc = sh * 64 + ((sp ^ kk) << 3) + grp;   // swizzled col
            #pragma unroll
            for (int g = 0; g < 2; g++) {
                const int p0 = g * 8 + kk;
                const uint2 b0 = BHL[p0 * PSTR + nloc];
                const uint2 b1 = BHL[(p0 + 4) * PSTR + nloc];
                #pragma unroll
                for (int m = 0; m < 2; m++) {
                    mma_bf16(acc[m], ah[m][g], b0.x, b1.x);
                    mma_bf16(acc[m], al[m][g], b0.x, b1.x);
                    mma_bf16(acc[m], ah[m][g], b0.y, b1.y);
                }
            }

            const int col = nb + sh * 64 + sp * 8 + kk * 2;
            #pragma unroll
            for (int m = 0; m < 2; m++) {
                const size_t r0 = (size_t)(m0 + rowg * 32 + m * 16 + grp);
                __stcs(reinterpret_cast<float2*>(C + r0 * CD + col),
                       make_float2(acc[m][0], acc[m][1]));
                __stcs(reinterpret_cast<float2*>(C + (r0 + 8) * CD + col),
                       make_float2(acc[m][2], acc[m][3]));
            }
        }
    }
}

// ---------------------------------------------------------------------------
// m_t = A @ mu (tiny)
// ---------------------------------------------------------------------------
__global__ __launch_bounds__(256)
void m_kernel(const float* __restrict__ alpha,
              const float* __restrict__ mu,
              const float* __restrict__ asc,
              float* __restrict__ m)
{
    __shared__ float mu_s[NS * NC];
    __shared__ float a_s[16 * NS];
    __shared__ float scale_s[NS];

    const int tid = threadIdx.x;
    if (tid < NS) scale_s[tid] = log1pf(expf(asc[tid]));
    __syncthreads();

    for (int i = tid; i < NS * NC; i += 256) mu_s[i] = mu[i];

    const int bt0 = blockIdx.x * 16;
    for (int i = tid; i < 16 * NS; i += 256) {
        const int r = i / NS, j = i % NS;
        a_s[i] = alpha[(bt0 + r) * NS + j] * scale_s[j];
    }
    __syncthreads();

    for (int o = tid; o < 16 * NC; o += 256) {
        const int r = o / NC, c = o % NC;
        float s = 0.0f;
        #pragma unroll
        for (int j = 0; j < NS; j++) s = fmaf(a_s[r * NS + j], mu_s[j * NC + c], s);
        m[(size_t)(bt0 + r) * NC + c] = s;
    }
}

extern "C" void kernel_launch(void* const* d_in, const int* in_sizes, int n_in,
                              void* d_out, int out_size)
{
    const float* alpha = (const float*)d_in[0];   // [64,400,25]
    const float* mu    = (const float*)d_in[1];   // [25,80]
    const float* D     = (const float*)d_in[2];   // [25,80,80]
    const float* asc   = (const float*)d_in[3];   // [25]

    float* out   = (float*)d_out;
    float* m_out = out;                 // [64,400,80]
    float* c_out = out + (BT * NC);     // [64,400,80,80]

    m_kernel<<<BT / 16, 256>>>(alpha, mu, asc, m_out);
    tc_kernel<<<dim3(NXB, NYB), THREADS>>>(alpha, D, asc, c_out);
}

// round 14
// speedup vs baseline: 1.4904x; 1.0044x over previous
#include <cuda_runtime.h>
#include <cstdint>

#define NS 25
#define NC 80
#define CD 6400
#define BT 25600

#define MTB 128              // M rows per tile
#define NTB 128              // N cols per stripe
#define THREADS 256
#define NXB 50               // C stripes
#define NYB 8                // 50*8 = 400 C blocks (+16 m blocks)
#define MTILES 200
#define NMB 16               // m blocks

#define PL 16                // k-pair planes
#define PSTR 132             // uint2 per plane

// dynamic smem layout (bytes)
#define OFF_AHL   0
#define OFF_BHL   (PL * PSTR * 8)                 // 16896
#define OFF_STAGE (2 * PL * PSTR * 8)             // 33792
#define OFF_SC    (OFF_STAGE + 8 * 512 * 8)       // 66560
#define SMB       (OFF_SC + 128)                  // 66688

__device__ __forceinline__ uint16_t f2bf(float v) {
    uint16_t r;
    asm("cvt.rn.bf16.f32 %0, %1;" : "=h"(r) : "f"(v));
    return r;
}
__device__ __forceinline__ float bf2f(uint16_t h) {
    return __uint_as_float((uint32_t)h << 16);
}
__device__ __forceinline__ void mma_bf16(float* acc, const uint32_t* a,
                                         uint32_t b0, uint32_t b1) {
    asm volatile(
        "mma.sync.aligned.m16n8k16.row.col.f32.bf16.bf16.f32 "
        "{%0,%1,%2,%3}, {%4,%5,%6,%7}, {%8,%9}, {%0,%1,%2,%3};"
        : "+f"(acc[0]), "+f"(acc[1]), "+f"(acc[2]), "+f"(acc[3])
        : "r"(a[0]), "r"(a[1]), "r"(a[2]), "r"(a[3]), "r"(b0), "r"(b1));
}
__device__ __forceinline__ int pidx(int plane, int x) {
    return plane * PSTR + (x ^ ((plane & 3) << 3));
}
__device__ __forceinline__ float softplus_f(float x) { return log1pf(expf(x)); }

// ---------------------------------------------------------------------------
__global__ __launch_bounds__(THREADS, 3)
void fused_kernel(const float* __restrict__ alpha,
                  const float* __restrict__ mu,
                  const float* __restrict__ D,
                  const float* __restrict__ asc,
                  float* __restrict__ m_out,
                  float* __restrict__ C)
{
    extern __shared__ char dsm[];
    const int tid = threadIdx.x;
    const int bx = blockIdx.x, by = blockIdx.y;

    if (bx >= NXB) {
        // =================== m path: m = A @ mu ===================
        float* mu_s = reinterpret_cast<float*>(dsm);          // 2000 floats
        float* a_s  = mu_s + 2048;                            // 3200 floats
        float* sc   = a_s + 3232;                             // 25 floats

        if (tid < NS) sc[tid] = softplus_f(asc[tid]);
        for (int i = tid; i < NS * NC; i += THREADS) mu_s[i] = mu[i];
        __syncthreads();

        const int active = (tid < 160);
        const int c = tid % 80, h = tid / 80;
        float mur[NS];
        if (active) {
            #pragma unroll
            for (int j = 0; j < NS; j++) mur[j] = mu_s[j * NC + c];
        }

        const int mid = (bx - NXB) + 2 * by;                  // 0..15
        for (int mt = mid; mt < MTILES; mt += NMB) {
            const int bt0 = mt * MTB;
            __syncthreads();
            const float* ap = alpha + (size_t)bt0 * NS;
            for (int i = tid; i < MTB * NS; i += THREADS) {
                const int j = i % NS;
                a_s[i] = ap[i] * sc[j];
            }
            __syncthreads();
            if (active) {
                #pragma unroll 4
                for (int rr = 0; rr < 64; rr++) {
                    const int r = h * 64 + rr;
                    float s = 0.f;
                    #pragma unroll
                    for (int j = 0; j < NS; j++) s = fmaf(a_s[r * NS + j], mur[j], s);
                    __stcs(&m_out[(size_t)(bt0 + r) * NC + c], s);
                }
            }
        }
        return;
    }

    // =================== C path: C = A @ D_flat ===================
    uint2*  AHL   = reinterpret_cast<uint2*>(dsm + OFF_AHL);
    uint2*  BHL   = reinterpret_cast<uint2*>(dsm + OFF_BHL);
    float2* stage = reinterpret_cast<float2*>(dsm + OFF_STAGE);
    float2* sc2   = reinterpret_cast<float2*>(dsm + OFF_SC);

    if (tid < 13) {
        const float s0 = softplus_f(asc[2 * tid]);
        const float s1 = (tid < 12) ? softplus_f(asc[2 * tid + 1]) : 0.f;
        sc2[tid] = make_float2(s0, s1);
    }
    // zero pad planes 13..15 (read by g=1, never written)
    for (int i = tid; i < 3 * PSTR; i += THREADS) {
        AHL[13 * PSTR + i] = make_uint2(0, 0);
        BHL[13 * PSTR + i] = make_uint2(0, 0);
    }

    const int nb = bx * NTB;

    // ---- B split (once per block): packed k-pairs, swizzled ----
    for (int it = tid; it < 13 * NTB; it += THREADS) {
        const int kp = it >> 7, n = it & 127;
        const float v0 = D[(size_t)(2 * kp) * CD + nb + n];
        const float v1 = (kp < 12) ? D[(size_t)(2 * kp + 1) * CD + nb + n] : 0.f;
        const uint16_t h0 = f2bf(v0), h1 = f2bf(v1);
        const uint16_t l0 = f2bf(v0 - bf2f(h0)), l1 = f2bf(v1 - bf2f(h1));
        BHL[pidx(kp, n)] = make_uint2((uint32_t)h0 | ((uint32_t)h1 << 16),
                                      (uint32_t)l0 | ((uint32_t)l1 << 16));
    }

    const int w = tid >> 5, lane = tid & 31;
    const int grp = lane >> 2, kk = lane & 3;
    const int rowg = w >> 1;
    const int sh   = w & 1;
    const int kkx  = kk << 3;

    // loop-invariant staging addresses
    float2* sb  = stage + w * 512;                      // this warp's 4 KB
    float*  sbf = reinterpret_cast<float*>(sb);
    const int rq  = lane >> 3, q = lane & 7;
    const int c2l = (2 * q) ^ ((rq & 3) << 2);          // drain LDS col (const/lane)
    const int swg = (grp & 3) << 2;                     // stage STS swizzle

    for (int mt = by; mt < MTILES; mt += NYB) {
        const int m0 = mt * MTB;

        __syncthreads();
        // ---- A split: pair-granular, LDG.32 x2 + STS.64 ----
        {
            const float* ap = alpha + (size_t)m0 * NS;
            for (int i = tid; i < MTB * 13; i += THREADS) {
                const int r = i / 13, kp = i - r * 13;
                const float2 s = sc2[kp];
                const float v0 = ap[r * NS + 2 * kp] * s.x;
                const float v1 = (kp < 12) ? ap[r * NS + 2 * kp + 1] * s.y : 0.f;
                const uint16_t h0 = f2bf(v0), h1 = f2bf(v1);
                const uint16_t l0 = f2bf(v0 - bf2f(h0)), l1 = f2bf(v1 - bf2f(h1));
                AHL[pidx(kp, r)] = make_uint2((uint32_t)h0 | ((uint32_t)h1 << 16),
                                              (uint32_t)l0 | ((uint32_t)l1 << 16));
            }
        }
        __syncthreads();

        // ---- a-fragments (hi+lo), register-resident ----
        uint32_t ah[2][2][4], al[2][2][4];
        #pragma unroll
        for (int m = 0; m < 2; m++) {
            const int rb = rowg * 32 + m * 16 + grp;
            #pragma unroll
            for (int g = 0; g < 2; g++) {
                const int p0 = g * 8 + kk;
                uint2 t;
                t = AHL[p0 * PSTR + ((rb)     ^ kkx)]; ah[m][g][0] = t.x; al[m][g][0] = t.y;
                t = AHL[p0 * PSTR + ((rb + 8) ^ kkx)]; ah[m][g][1] = t.x; al[m][g][1] = t.y;
                t = AHL[(p0 + 4) * PSTR + ((rb)     ^ kkx)]; ah[m][g][2] = t.x; al[m][g][2] = t.y;
                t = AHL[(p0 + 4) * PSTR + ((rb + 8) ^ kkx)]; ah[m][g][3] = t.x; al[m][g][3] = t.y;
            }
        }

        float* Crow = C + (size_t)(m0 + rowg * 32) * CD + nb + sh * 64;

        #pragma unroll
        for (int half = 0; half < 2; half++) {
            #pragma unroll
            for (int spi = 0; spi < 4; spi++) {
                const int sp = half * 4 + spi;
                float acc[2][4];
                #pragma unroll
                for (int m = 0; m < 2; m++)
                    #pragma unroll
                    for (int t2 = 0; t2 < 4; t2++) acc[m][t2] = 0.f;

                const int nloc = sh * 64 + ((sp ^ kk) << 3) + grp;
                #pragma unroll
                for (int g = 0; g < 2; g++) {
                    const int p0 = g * 8 + kk;
                    const uint2 b0 = BHL[p0 * PSTR + nloc];
                    const uint2 b1 = BHL[(p0 + 4) * PSTR + nloc];
                    #pragma unroll
                    for (int m = 0; m < 2; m++) {
                        mma_bf16(acc[m], ah[m][g], b0.x, b1.x);
                        mma_bf16(acc[m], al[m][g], b0.x, b1.x);
                        mma_bf16(acc[m], ah[m][g], b0.y, b1.y);
                    }
                }

                // stage this sp (conflict-free STS.64 x4)
                const int c2s = (spi * 4 + kk) ^ swg;
                sb[(grp)      * 16 + c2s] = make_float2(acc[0][0], acc[0][1]);
                sb[(grp + 8)  * 16 + c2s] = make_float2(acc[0][2], acc[0][3]);
                sb[(grp + 16) * 16 + c2s] = make_float2(acc[1][0], acc[1][1]);
                sb[(grp + 24) * 16 + c2s] = make_float2(acc[1][2], acc[1][3]);
            }
            __syncwarp();

            // drain: 8 LDS.128 + 8 fully-coalesced STG.128 (full 128B lines)
            float* Cst = Crow + half * 32 + q * 4;
            #pragma unroll
            for (int it = 0; it < 8; it++) {
                const int r = 4 * it + rq;
                const float4 v = *reinterpret_cast<const float4*>(sbf + r * 32 + c2l * 2);
                __stcs(reinterpret_cast<float4*>(Cst + (size_t)r * CD), v);
            }
            __syncwarp();
        }
    }
}

extern "C" void kernel_launch(void* const* d_in, const int* in_sizes, int n_in,
                              void* d_out, int out_size)
{
    const float* alpha = (const float*)d_in[0];   // [64,400,25]
    const float* mu    = (const float*)d_in[1];   // [25,80]
    const float* D     = (const float*)d_in[2];   // [25,80,80]
    const float* asc   = (const float*)d_in[3];   // [25]

    float* out   = (float*)d_out;
    float* m_o   = out;                 // [64,400,80]
    float* c_o   = out + (BT * NC);     // [64,400,80,80]

    static int inited = 0;
    if (!inited) {
        cudaFuncSetAttribute(fused_kernel,
                             cudaFuncAttributeMaxDynamicSharedMemorySize, SMB);
        inited = 1;
    }

    fused_kernel<<<dim3(NXB + 2, NYB), THREADS, SMB>>>(alpha, mu, D, asc, m_o, c_o);
}